// round 12
// baseline (speedup 1.0000x reference)
#include <cuda_runtime.h>
#include <cstdint>

#define NN     16000
#define IN_DIM 128
#define HID    64
#define BB     32
#define PP     128
#define DD     100
#define NCLS   10
#define INV_PI 0.31830988618379067f

// ---------------- scratch (device globals; no allocation allowed) -----------
__device__ float    g_filt[NN];
__device__ float    g_imgs[BB * 2 * DD * DD];    // UNNORMALIZED pers images
__device__ unsigned g_immax[BB * 2];             // per image-channel max (fp bits)
__device__ float    g_y1[BB * 16 * 50 * 50];
__device__ float    g_y2[BB * 32 * 25 * 25];

// ======================= K1: node filtration MLP ============================
__global__ __launch_bounds__(256) void filt_kernel(
    const float* __restrict__ x, const float* __restrict__ w1,
    const float* __restrict__ b1, const float* __restrict__ w2,
    const float* __restrict__ b2, float* __restrict__ out_filt)
{
    const int tid   = threadIdx.x;
    if (blockIdx.x == 0 && tid < BB * 2) g_immax[tid] = 0u;  // reset maxes
    const int j     = tid & 63;
    const int chunk = tid >> 6;

    float wr[32];
    #pragma unroll
    for (int k = 0; k < 32; ++k)
        wr[k] = w1[(chunk * 32 + k) * HID + j];
    const float b1j = b1[j];
    const float w2j = w2[j];
    const float b2v = b2[0];

    __shared__ float xs[4][IN_DIM];
    __shared__ float part[4][4 * 64];
    __shared__ float nsum[4][2];

    for (int grp = 0; grp < 16; ++grp) {
        const int nbase = blockIdx.x * 64 + grp * 4;
        __syncthreads();
        for (int idx = tid; idx < 4 * IN_DIM; idx += 256) {
            int n = idx >> 7, c = idx & 127;
            xs[n][c] = x[(nbase + n) * IN_DIM + c];
        }
        __syncthreads();

        #pragma unroll
        for (int n = 0; n < 4; ++n) {
            const float4* xp = reinterpret_cast<const float4*>(xs[n] + chunk * 32);
            float s = 0.f;
            #pragma unroll
            for (int q = 0; q < 8; ++q) {
                float4 v = xp[q];
                s += v.x * wr[4 * q] + v.y * wr[4 * q + 1]
                   + v.z * wr[4 * q + 2] + v.w * wr[4 * q + 3];
            }
            part[n][chunk * 64 + j] = s;
        }
        __syncthreads();

        {
            const int n2 = chunk;
            float v = part[n2][j] + part[n2][64 + j]
                    + part[n2][128 + j] + part[n2][192 + j] + b1j;
            float h = fmaxf(v, 0.f) * w2j;
            #pragma unroll
            for (int off = 16; off; off >>= 1)
                h += __shfl_down_sync(0xffffffffu, h, off);
            if ((j & 31) == 0) nsum[n2][j >> 5] = h;
        }
        __syncthreads();
        if (tid < 4) {
            const int node = nbase + tid;
            float t = nsum[tid][0] + nsum[tid][1] + b2v;
            float f = 1.f / (1.f + __expf(-t));
            g_filt[node]   = f;
            out_filt[node] = f;
        }
    }
}

// ================ K2: persistence image (quarter blocks, atomic max) ========
#define P_UW 28
#define PERS_SMEM_FLOATS (PP * P_UW + PP * DD + PP + PP + 32)
__global__ __launch_bounds__(256) void pers_image_kernel(
    const int* __restrict__ pidx0, const int* __restrict__ pidx1)
{
    extern __shared__ float sm[];
    float* Us = sm;                 // [128][28]
    float* Vs = Us + PP * P_UW;     // [128][100]
    float* bs = Vs + PP * DD;
    float* ps = bs + PP;
    float* red = ps + PP;

    const int m     = blockIdx.x;
    const int imgch = m >> 2;
    const int q     = m & 3;
    const int b  = imgch >> 1;
    const int ch = imgch & 1;
    const int* pidx = ch ? pidx1 : pidx0;
    const int tid = threadIdx.x;

    const int itile0  = (q == 0) ? 0 : (7 + 6 * (q - 1));   // 0,7,13,19
    const int ntilesI = (q == 0) ? 7 : 6;
    const int ibase   = itile0 * 4;
    const int iwidth  = ntilesI * 4;

    if (tid < PP) {
        int i0 = pidx[(b * PP + tid) * 2 + 0];
        int i1 = pidx[(b * PP + tid) * 2 + 1];
        float birth = g_filt[i0];
        bs[tid] = birth;
        ps[tid] = g_filt[i1] - birth;
    }
    __syncthreads();

    for (int idx = tid; idx < PP * P_UW; idx += 256) {
        int p = idx / P_UW, t = idx % P_UW;
        float c  = (float)(ibase + t) * 0.01f;
        float db = bs[p] - c;
        Us[idx] = (t < iwidth) ? __expf(-db * db) : 0.f;
    }
    for (int idx = tid; idx < PP * DD; idx += 256) {
        int p = idx / DD, t = idx % DD;
        float c  = (float)t * 0.01f;
        float dp = ps[p] - c;
        Vs[idx] = INV_PI * __expf(-dp * dp);
    }
    __syncthreads();

    const int nt = ntilesI * 25;
    float acc[16];
    float mx = 0.f;
    int i0 = 0, j0 = 0;
    if (tid < nt) {
        i0 = (tid / 25) * 4;
        j0 = (tid % 25) * 4;
        #pragma unroll
        for (int k = 0; k < 16; ++k) acc[k] = 0.f;
        #pragma unroll 4
        for (int p = 0; p < PP; ++p) {
            float4 u = *reinterpret_cast<const float4*>(Us + p * P_UW + i0);
            float4 v = *reinterpret_cast<const float4*>(Vs + p * DD + j0);
            acc[0]  += u.x * v.x; acc[1]  += u.x * v.y; acc[2]  += u.x * v.z; acc[3]  += u.x * v.w;
            acc[4]  += u.y * v.x; acc[5]  += u.y * v.y; acc[6]  += u.y * v.z; acc[7]  += u.y * v.w;
            acc[8]  += u.z * v.x; acc[9]  += u.z * v.y; acc[10] += u.z * v.z; acc[11] += u.z * v.w;
            acc[12] += u.w * v.x; acc[13] += u.w * v.y; acc[14] += u.w * v.z; acc[15] += u.w * v.w;
        }
        #pragma unroll
        for (int k = 0; k < 16; ++k) mx = fmaxf(mx, acc[k]);
    }
    #pragma unroll
    for (int off = 16; off; off >>= 1)
        mx = fmaxf(mx, __shfl_down_sync(0xffffffffu, mx, off));
    if ((tid & 31) == 0) red[tid >> 5] = mx;
    __syncthreads();
    if (tid == 0) {
        float t = red[0];
        #pragma unroll
        for (int w = 1; w < 8; ++w) t = fmaxf(t, red[w]);
        atomicMax(&g_immax[imgch], __float_as_uint(t));
    }

    if (tid < nt) {
        float* outp = g_imgs + imgch * (DD * DD);
        #pragma unroll
        for (int a = 0; a < 4; ++a)
            #pragma unroll
            for (int c = 0; c < 4; ++c)
                outp[(ibase + i0 + a) * DD + (j0 + c)] = acc[a * 4 + c];
    }
}

// ================== tf32 helpers (shared by both TC convs) ==================
__device__ __forceinline__ uint32_t to_tf32(float x) {
    uint32_t r;
    asm("cvt.rna.tf32.f32 %0, %1;" : "=r"(r) : "f"(x));
    return r;
}
__device__ __forceinline__ void mma_tf32(
    float* d, const uint32_t* a, const uint32_t* b)
{
    asm volatile(
        "mma.sync.aligned.m16n8k8.row.col.f32.tf32.tf32.f32 "
        "{%0,%1,%2,%3}, {%4,%5,%6,%7}, {%8,%9}, {%0,%1,%2,%3};\n"
        : "+f"(d[0]), "+f"(d[1]), "+f"(d[2]), "+f"(d[3])
        : "r"(a[0]), "r"(a[1]), "r"(a[2]), "r"(a[3]),
          "r"(b[0]), "r"(b[1]));
}

// ============= K3: conv1 tf32 TC implicit GEMM (+fused normalization) =======
#define C1_TR   14
#define C1_WP   104
#define C1_TILE (2 * C1_TR * C1_WP)            // 2912
#define C1_CS   (1008 * 17)                    // 17136
#define C1_SMEM_FLOATS (C1_CS + 16)
__global__ __launch_bounds__(256, 2) void conv1_tc_kernel(
    const float* __restrict__ wts, const float* __restrict__ bias)
{
    extern __shared__ float s[];
    float* tile = s;                           // [2][14][104] (mainloop)
    float* Bf   = tile + C1_TILE;              // [7][32][4]
    int*   offs = (int*)(Bf + 7 * 32 * 4);     // [56]
    float* Cs   = s;                           // [1008][17] (post-mainloop)
    float* bsm  = s + C1_CS;                   // [16]

    const int img = blockIdx.x;
    const int rg  = blockIdx.y;
    const int tid = threadIdx.x;
    const int lane = tid & 31, warp = tid >> 5;
    const int grp = lane >> 2, qid = lane & 3;

    if (tid < 224) {
        const int ks = tid >> 5, ln = tid & 31;
        const int g2 = ln >> 2, q2 = ln & 3;
        float v[4];
        #pragma unroll
        for (int nt = 0; nt < 2; ++nt)
            #pragma unroll
            for (int h = 0; h < 2; ++h) {
                const int k = 8 * ks + q2 + 4 * h;
                v[2 * nt + h] = (k < 50)
                    ? __uint_as_float(to_tf32(wts[(g2 + 8 * nt) * 50 + k])) : 0.f;
            }
        *reinterpret_cast<float4*>(Bf + tid * 4) = *reinterpret_cast<float4*>(v);
    }
    if (tid < 16) bsm[tid] = bias[tid];
    if (tid < 56) {
        const int ic = tid / 25, tap = tid % 25;
        offs[tid] = (tid < 50)
            ? ic * (C1_TR * C1_WP) + (tap / 5) * C1_WP + (tap % 5) : 0;
    }

    const float inv0 = 1.f / __uint_as_float(g_immax[img * 2]);
    const float inv1 = 1.f / __uint_as_float(g_immax[img * 2 + 1]);
    const int iy0 = 10 * rg - 2;
    for (int i = tid; i < C1_TILE; i += 256) {
        const int ic = i / (C1_TR * C1_WP);
        const int r  = (i / C1_WP) % C1_TR;
        const int c  = i % C1_WP;
        const int iy = iy0 + r, ix = c - 2;
        float v = 0.f;
        if (iy >= 0 && iy < 100 && ix >= 0 && ix < 100)
            v = g_imgs[(img * 2 + ic) * (DD * DD) + iy * DD + ix]
                * (ic ? inv1 : inv0);
        tile[i] = __uint_as_float(to_tf32(v));
    }
    __syncthreads();

    int abase[8][2];
    #pragma unroll
    for (int t = 0; t < 8; ++t) {
        const int mt = warp + 8 * t;
        #pragma unroll
        for (int h = 0; h < 2; ++h) {
            int m = mt * 16 + grp + 8 * h;
            if (m > 999) m = 999;
            abase[t][h] = (m / 100) * C1_WP + (m % 100);
        }
    }

    float acc[8][2][4];
    #pragma unroll
    for (int t = 0; t < 8; ++t)
        #pragma unroll
        for (int nt = 0; nt < 2; ++nt)
            acc[t][nt][0] = acc[t][nt][1] = acc[t][nt][2] = acc[t][nt][3] = 0.f;

    #pragma unroll
    for (int ks = 0; ks < 7; ++ks) {
        const int o0 = offs[ks * 8 + qid];
        const int o1 = offs[ks * 8 + qid + 4];
        const float4 bv = *reinterpret_cast<const float4*>(
            Bf + (ks * 32 + lane) * 4);
        uint32_t b[2][2];
        b[0][0] = __float_as_uint(bv.x); b[0][1] = __float_as_uint(bv.y);
        b[1][0] = __float_as_uint(bv.z); b[1][1] = __float_as_uint(bv.w);

        #pragma unroll
        for (int t = 0; t < 8; ++t) {
            if (warp + 8 * t < 63) {
                uint32_t a[4];
                a[0] = __float_as_uint(tile[abase[t][0] + o0]);
                a[1] = __float_as_uint(tile[abase[t][1] + o0]);
                a[2] = __float_as_uint(tile[abase[t][0] + o1]);
                a[3] = __float_as_uint(tile[abase[t][1] + o1]);
                mma_tf32(acc[t][0], a, b[0]);
                mma_tf32(acc[t][1], a, b[1]);
            }
        }
    }
    __syncthreads();

    #pragma unroll
    for (int t = 0; t < 8; ++t) {
        const int mt = warp + 8 * t;
        if (mt < 63) {
            const int m0 = mt * 16 + grp;
            #pragma unroll
            for (int nt = 0; nt < 2; ++nt) {
                const int n0 = nt * 8 + 2 * qid;
                Cs[m0 * 17 + n0]           = acc[t][nt][0];
                Cs[m0 * 17 + n0 + 1]       = acc[t][nt][1];
                Cs[(m0 + 8) * 17 + n0]     = acc[t][nt][2];
                Cs[(m0 + 8) * 17 + n0 + 1] = acc[t][nt][3];
            }
        }
    }
    __syncthreads();

    for (int idx = tid; idx < 4000; idx += 256) {
        const int oc = idx & 15;
        const int pc = (idx >> 4) % 50;
        const int prl = idx / 800;
        const int prow = 5 * rg + prl;
        const int m00 = 2 * prl * 100 + 2 * pc;
        float v = fmaxf(fmaxf(Cs[m00 * 17 + oc],         Cs[(m00 + 1) * 17 + oc]),
                        fmaxf(Cs[(m00 + 100) * 17 + oc], Cs[(m00 + 101) * 17 + oc]));
        v = fmaxf(v + bsm[oc], 0.f);
        g_y1[((img * 16 + oc) * 50 + prow) * 50 + pc] = v;
    }
}

// ============= K4: conv2 tf32 TC, 384 threads (24 warps/SM) =================
// 12 warps per CTA, each owns m-tiles {w, w+12} (valid mt<19) -> acc 32 regs,
// fits the 85-reg budget of 768 threads/SM. Same math/layout as R9.
#define C2_TR   10
#define C2_TILE (16 * C2_TR * 57)                           // 9120
#define C2_SMEM_FLOATS (C2_TILE + 50 * 32 * 8 + 400 + 32)   // 22352
__global__ __launch_bounds__(384, 2) void conv2_tc_kernel(
    const float* __restrict__ wts, const float* __restrict__ bias)
{
    extern __shared__ float s[];
    float* tile = s;                          // [16][10][57]
    float* Bf   = tile + C2_TILE;             // [50][32][8]
    int*   offs = (int*)(Bf + 50 * 32 * 8);   // [400]
    float* bsm  = (float*)(offs + 400);       // [32]
    float* Cs   = s;                          // [304][33] alias (post-mainloop)

    const int img = blockIdx.x;
    const int rg  = blockIdx.y;               // 3-pooled-row group (0..8)
    const int tid = threadIdx.x;
    const int lane = tid & 31, warp = tid >> 5;   // warp 0..11
    const int grp = lane >> 2, qid = lane & 3;

    for (int idx = tid; idx < 50 * 32; idx += blockDim.x) {
        const int ks = idx >> 5, ln = idx & 31;
        const int g2 = ln >> 2, q2 = ln & 3;
        float v[8];
        #pragma unroll
        for (int nt = 0; nt < 4; ++nt) {
            const float* wp = wts + (g2 + 8 * nt) * 400 + 8 * ks + q2;
            v[2 * nt]     = __uint_as_float(to_tf32(wp[0]));
            v[2 * nt + 1] = __uint_as_float(to_tf32(wp[4]));
        }
        float* dst = Bf + idx * 8;
        *reinterpret_cast<float4*>(dst)     = *reinterpret_cast<float4*>(v);
        *reinterpret_cast<float4*>(dst + 4) = *reinterpret_cast<float4*>(v + 4);
    }
    if (tid < 32) bsm[tid] = bias[tid];
    for (int k = tid; k < 400; k += blockDim.x) {
        int ic = k / 25, kk = k % 25;
        offs[k] = ic * (C2_TR * 57) + (kk / 5) * 57 + (kk % 5);
    }
    const int iy0 = 6 * rg - 2;
    for (int i = tid; i < C2_TILE; i += blockDim.x) {
        int ic = i / (C2_TR * 57), r = (i / 57) % C2_TR, c = i % 57;
        int iy = iy0 + r, ix = c - 2;
        float v = 0.f;
        if (iy >= 0 && iy < 50 && ix >= 0 && ix < 50)
            v = g_y1[((img * 16 + ic) * 50 + iy) * 50 + ix];
        tile[i] = __uint_as_float(to_tf32(v));
    }
    __syncthreads();

    // m-tiles {warp, warp+12}; t=1 valid iff warp < 7
    int abase[2][2];
    const int nvalid = (warp < 7) ? 2 : 1;
    #pragma unroll
    for (int t = 0; t < 2; ++t) {
        const int mt = warp + 12 * t;
        #pragma unroll
        for (int h = 0; h < 2; ++h) {
            int m = mt * 16 + grp + h * 8;
            if (m > 299) m = 299;
            abase[t][h] = (m / 50) * 57 + (m % 50);
        }
    }

    float acc[2][4][4];
    #pragma unroll
    for (int t = 0; t < 2; ++t)
        #pragma unroll
        for (int nt = 0; nt < 4; ++nt)
            acc[t][nt][0] = acc[t][nt][1] = acc[t][nt][2] = acc[t][nt][3] = 0.f;

    #pragma unroll 2
    for (int ks = 0; ks < 50; ++ks) {
        const int o0 = offs[ks * 8 + qid];
        const int o1 = offs[ks * 8 + qid + 4];

        const float4* bp = reinterpret_cast<const float4*>(
            Bf + (ks * 32 + lane) * 8);
        float4 bv0 = bp[0], bv1 = bp[1];
        uint32_t b[4][2];
        b[0][0] = __float_as_uint(bv0.x); b[0][1] = __float_as_uint(bv0.y);
        b[1][0] = __float_as_uint(bv0.z); b[1][1] = __float_as_uint(bv0.w);
        b[2][0] = __float_as_uint(bv1.x); b[2][1] = __float_as_uint(bv1.y);
        b[3][0] = __float_as_uint(bv1.z); b[3][1] = __float_as_uint(bv1.w);

        #pragma unroll
        for (int t = 0; t < 2; ++t) {
            if (t < nvalid) {
                uint32_t a[4];
                a[0] = __float_as_uint(tile[abase[t][0] + o0]);
                a[1] = __float_as_uint(tile[abase[t][1] + o0]);
                a[2] = __float_as_uint(tile[abase[t][0] + o1]);
                a[3] = __float_as_uint(tile[abase[t][1] + o1]);
                #pragma unroll
                for (int nt = 0; nt < 4; ++nt)
                    mma_tf32(acc[t][nt], a, b[nt]);
            }
        }
    }

    __syncthreads();   // tile/Bf reads done; Cs may overwrite

    #pragma unroll
    for (int t = 0; t < 2; ++t) {
        const int mt = warp + 12 * t;
        if (mt < 19) {
            const int m0 = mt * 16 + grp;
            #pragma unroll
            for (int nt = 0; nt < 4; ++nt) {
                const int n0 = nt * 8 + 2 * qid;
                Cs[m0 * 33 + n0]           = acc[t][nt][0];
                Cs[m0 * 33 + n0 + 1]       = acc[t][nt][1];
                Cs[(m0 + 8) * 33 + n0]     = acc[t][nt][2];
                Cs[(m0 + 8) * 33 + n0 + 1] = acc[t][nt][3];
            }
        }
    }
    __syncthreads();

    for (int idx = tid; idx < 2400; idx += blockDim.x) {
        const int oc = idx & 31;
        const int pc = (idx >> 5) % 25;
        const int prl = idx / 800;
        const int prow = 3 * rg + prl;
        if (prow < 25) {
            const int m00 = 2 * prl * 50 + 2 * pc;
            float v = fmaxf(fmaxf(Cs[m00 * 33 + oc],        Cs[(m00 + 1) * 33 + oc]),
                            fmaxf(Cs[(m00 + 50) * 33 + oc], Cs[(m00 + 51) * 33 + oc]));
            v = fmaxf(v + bsm[oc], 0.f);
            g_y2[((img * 32 + oc) * 25 + prow) * 25 + pc] = v;
        }
    }
}

// ======================= K5: FC head ========================================
__global__ __launch_bounds__(256) void fc_kernel(
    const float* __restrict__ w, const float* __restrict__ b,
    float* __restrict__ out)
{
    const int bc = blockIdx.x;
    const int bi = bc / NCLS, c = bc % NCLS;
    const float4* yb = reinterpret_cast<const float4*>(g_y2 + bi * 20000);
    const float4* wc = reinterpret_cast<const float4*>(w + c * 20000);
    float s = 0.f;
    for (int k = threadIdx.x; k < 5000; k += 256) {
        float4 a = yb[k], ww = wc[k];
        s += a.x * ww.x + a.y * ww.y + a.z * ww.z + a.w * ww.w;
    }
    #pragma unroll
    for (int off = 16; off; off >>= 1)
        s += __shfl_down_sync(0xffffffffu, s, off);
    __shared__ float red[8];
    if ((threadIdx.x & 31) == 0) red[threadIdx.x >> 5] = s;
    __syncthreads();
    if (threadIdx.x == 0) {
        float t = 0.f;
        #pragma unroll
        for (int wi = 0; wi < 8; ++wi) t += red[wi];
        out[bi * NCLS + c] = t + b[c];
    }
}

// ============================== launch ======================================
extern "C" void kernel_launch(void* const* d_in, const int* in_sizes, int n_in,
                              void* d_out, int out_size)
{
    const float* x        = (const float*)d_in[0];
    const int*   pidx0    = (const int*)  d_in[1];
    const int*   pidx1    = (const int*)  d_in[2];
    const float* w1       = (const float*)d_in[3];
    const float* b1       = (const float*)d_in[4];
    const float* w2       = (const float*)d_in[5];
    const float* b2       = (const float*)d_in[6];
    const float* conv1_w  = (const float*)d_in[7];
    const float* conv1_b  = (const float*)d_in[8];
    const float* conv2_w  = (const float*)d_in[9];
    const float* conv2_b  = (const float*)d_in[10];
    const float* out_w    = (const float*)d_in[11];
    const float* out_b    = (const float*)d_in[12];
    float* out = (float*)d_out;

    const int pers_smem  = PERS_SMEM_FLOATS * 4;   // 66816
    const int conv1_smem = C1_SMEM_FLOATS * 4;     // 68608
    const int conv2_smem = C2_SMEM_FLOATS * 4;     // 89408

    cudaFuncSetAttribute(pers_image_kernel,
        cudaFuncAttributeMaxDynamicSharedMemorySize, pers_smem);
    cudaFuncSetAttribute(conv1_tc_kernel,
        cudaFuncAttributeMaxDynamicSharedMemorySize, conv1_smem);
    cudaFuncSetAttribute(conv2_tc_kernel,
        cudaFuncAttributeMaxDynamicSharedMemorySize, conv2_smem);

    // K1: node filtration -> g_filt and d_out[320:]  (also resets g_immax)
    filt_kernel<<<250, 256>>>(x, w1, b1, w2, b2, out + BB * NCLS);

    // K2: persistence images (unnormalized) + per-imgch max, 256 blocks
    pers_image_kernel<<<256, 256, pers_smem>>>(pidx0, pidx1);

    // K3: conv1 via tf32 TC (+fused normalization) -> g_y1
    conv1_tc_kernel<<<dim3(32, 10), 256, conv1_smem>>>(conv1_w, conv1_b);

    // K4: conv2 via tf32 TC, 384-thread CTAs (24 warps/SM) -> g_y2
    conv2_tc_kernel<<<dim3(32, 9), 384, conv2_smem>>>(conv2_w, conv2_b);

    // K5: FC -> d_out[0:320]
    fc_kernel<<<BB * NCLS, 256>>>(out_w, out_b, out);
}

// round 14
// speedup vs baseline: 1.0828x; 1.0828x over previous
#include <cuda_runtime.h>
#include <cstdint>

#define NN     16000
#define IN_DIM 128
#define HID    64
#define BB     32
#define PP     128
#define DD     100
#define NCLS   10
#define INV_PI 0.31830988618379067f

// ---------------- scratch (device globals; no allocation allowed) -----------
__device__ float    g_filt[NN];
__device__ float    g_imgs[BB * 2 * DD * DD];    // UNNORMALIZED pers images
__device__ unsigned g_immax[BB * 2];             // per image-channel max (fp bits)
__device__ float    g_y1[BB * 16 * 50 * 50];

// ======================= K1: node filtration MLP ============================
// Also zeroes out[0:320] (y_hat accumulators) and g_immax.
__global__ __launch_bounds__(256) void filt_kernel(
    const float* __restrict__ x, const float* __restrict__ w1,
    const float* __restrict__ b1, const float* __restrict__ w2,
    const float* __restrict__ b2, float* __restrict__ out)
{
    const int tid   = threadIdx.x;
    if (blockIdx.x == 0) {
        if (tid < BB * 2) g_immax[tid] = 0u;
        for (int i = tid; i < BB * NCLS; i += 256) out[i] = 0.f;
    }
    const int j     = tid & 63;
    const int chunk = tid >> 6;

    float wr[32];
    #pragma unroll
    for (int k = 0; k < 32; ++k)
        wr[k] = w1[(chunk * 32 + k) * HID + j];
    const float b1j = b1[j];
    const float w2j = w2[j];
    const float b2v = b2[0];

    __shared__ float xs[4][IN_DIM];
    __shared__ float part[4][4 * 64];
    __shared__ float nsum[4][2];

    for (int grp = 0; grp < 16; ++grp) {
        const int nbase = blockIdx.x * 64 + grp * 4;
        __syncthreads();
        for (int idx = tid; idx < 4 * IN_DIM; idx += 256) {
            int n = idx >> 7, c = idx & 127;
            xs[n][c] = x[(nbase + n) * IN_DIM + c];
        }
        __syncthreads();

        #pragma unroll
        for (int n = 0; n < 4; ++n) {
            const float4* xp = reinterpret_cast<const float4*>(xs[n] + chunk * 32);
            float s = 0.f;
            #pragma unroll
            for (int q = 0; q < 8; ++q) {
                float4 v = xp[q];
                s += v.x * wr[4 * q] + v.y * wr[4 * q + 1]
                   + v.z * wr[4 * q + 2] + v.w * wr[4 * q + 3];
            }
            part[n][chunk * 64 + j] = s;
        }
        __syncthreads();

        {
            const int n2 = chunk;
            float v = part[n2][j] + part[n2][64 + j]
                    + part[n2][128 + j] + part[n2][192 + j] + b1j;
            float h = fmaxf(v, 0.f) * w2j;
            #pragma unroll
            for (int off = 16; off; off >>= 1)
                h += __shfl_down_sync(0xffffffffu, h, off);
            if ((j & 31) == 0) nsum[n2][j >> 5] = h;
        }
        __syncthreads();
        if (tid < 4) {
            const int node = nbase + tid;
            float t = nsum[tid][0] + nsum[tid][1] + b2v;
            float f = 1.f / (1.f + __expf(-t));
            g_filt[node]        = f;
            out[BB * NCLS + node] = f;
        }
    }
}

// ================ K2: persistence image (quarter blocks, atomic max) ========
#define P_UW 28
#define PERS_SMEM_FLOATS (PP * P_UW + PP * DD + PP + PP + 32)
__global__ __launch_bounds__(256) void pers_image_kernel(
    const int* __restrict__ pidx0, const int* __restrict__ pidx1)
{
    extern __shared__ float sm[];
    float* Us = sm;                 // [128][28]
    float* Vs = Us + PP * P_UW;     // [128][100]
    float* bs = Vs + PP * DD;
    float* ps = bs + PP;
    float* red = ps + PP;

    const int m     = blockIdx.x;
    const int imgch = m >> 2;
    const int q     = m & 3;
    const int b  = imgch >> 1;
    const int ch = imgch & 1;
    const int* pidx = ch ? pidx1 : pidx0;
    const int tid = threadIdx.x;

    const int itile0  = (q == 0) ? 0 : (7 + 6 * (q - 1));   // 0,7,13,19
    const int ntilesI = (q == 0) ? 7 : 6;
    const int ibase   = itile0 * 4;
    const int iwidth  = ntilesI * 4;

    if (tid < PP) {
        int i0 = pidx[(b * PP + tid) * 2 + 0];
        int i1 = pidx[(b * PP + tid) * 2 + 1];
        float birth = g_filt[i0];
        bs[tid] = birth;
        ps[tid] = g_filt[i1] - birth;
    }
    __syncthreads();

    for (int idx = tid; idx < PP * P_UW; idx += 256) {
        int p = idx / P_UW, t = idx % P_UW;
        float c  = (float)(ibase + t) * 0.01f;
        float db = bs[p] - c;
        Us[idx] = (t < iwidth) ? __expf(-db * db) : 0.f;
    }
    for (int idx = tid; idx < PP * DD; idx += 256) {
        int p = idx / DD, t = idx % DD;
        float c  = (float)t * 0.01f;
        float dp = ps[p] - c;
        Vs[idx] = INV_PI * __expf(-dp * dp);
    }
    __syncthreads();

    const int nt = ntilesI * 25;
    float acc[16];
    float mx = 0.f;
    int i0 = 0, j0 = 0;
    if (tid < nt) {
        i0 = (tid / 25) * 4;
        j0 = (tid % 25) * 4;
        #pragma unroll
        for (int k = 0; k < 16; ++k) acc[k] = 0.f;
        #pragma unroll 4
        for (int p = 0; p < PP; ++p) {
            float4 u = *reinterpret_cast<const float4*>(Us + p * P_UW + i0);
            float4 v = *reinterpret_cast<const float4*>(Vs + p * DD + j0);
            acc[0]  += u.x * v.x; acc[1]  += u.x * v.y; acc[2]  += u.x * v.z; acc[3]  += u.x * v.w;
            acc[4]  += u.y * v.x; acc[5]  += u.y * v.y; acc[6]  += u.y * v.z; acc[7]  += u.y * v.w;
            acc[8]  += u.z * v.x; acc[9]  += u.z * v.y; acc[10] += u.z * v.z; acc[11] += u.z * v.w;
            acc[12] += u.w * v.x; acc[13] += u.w * v.y; acc[14] += u.w * v.z; acc[15] += u.w * v.w;
        }
        #pragma unroll
        for (int k = 0; k < 16; ++k) mx = fmaxf(mx, acc[k]);
    }
    #pragma unroll
    for (int off = 16; off; off >>= 1)
        mx = fmaxf(mx, __shfl_down_sync(0xffffffffu, mx, off));
    if ((tid & 31) == 0) red[tid >> 5] = mx;
    __syncthreads();
    if (tid == 0) {
        float t = red[0];
        #pragma unroll
        for (int w = 1; w < 8; ++w) t = fmaxf(t, red[w]);
        atomicMax(&g_immax[imgch], __float_as_uint(t));
    }

    if (tid < nt) {
        float* outp = g_imgs + imgch * (DD * DD);
        #pragma unroll
        for (int a = 0; a < 4; ++a)
            #pragma unroll
            for (int c = 0; c < 4; ++c)
                outp[(ibase + i0 + a) * DD + (j0 + c)] = acc[a * 4 + c];
    }
}

// ================== tf32 helpers (shared by both TC convs) ==================
__device__ __forceinline__ uint32_t to_tf32(float x) {
    uint32_t r;
    asm("cvt.rna.tf32.f32 %0, %1;" : "=r"(r) : "f"(x));
    return r;
}
__device__ __forceinline__ void mma_tf32(
    float* d, const uint32_t* a, const uint32_t* b)
{
    asm volatile(
        "mma.sync.aligned.m16n8k8.row.col.f32.tf32.tf32.f32 "
        "{%0,%1,%2,%3}, {%4,%5,%6,%7}, {%8,%9}, {%0,%1,%2,%3};\n"
        : "+f"(d[0]), "+f"(d[1]), "+f"(d[2]), "+f"(d[3])
        : "r"(a[0]), "r"(a[1]), "r"(a[2]), "r"(a[3]),
          "r"(b[0]), "r"(b[1]));
}

// ============= K3: conv1 tf32 TC implicit GEMM (+fused normalization) =======
#define C1_TR   14
#define C1_WP   104
#define C1_TILE (2 * C1_TR * C1_WP)            // 2912
#define C1_CS   (1008 * 17)                    // 17136
#define C1_SMEM_FLOATS (C1_CS + 16)
__global__ __launch_bounds__(256, 2) void conv1_tc_kernel(
    const float* __restrict__ wts, const float* __restrict__ bias)
{
    extern __shared__ float s[];
    float* tile = s;                           // [2][14][104] (mainloop)
    float* Bf   = tile + C1_TILE;              // [7][32][4]
    int*   offs = (int*)(Bf + 7 * 32 * 4);     // [56]
    float* Cs   = s;                           // [1008][17] (post-mainloop)
    float* bsm  = s + C1_CS;                   // [16]

    const int img = blockIdx.x;
    const int rg  = blockIdx.y;
    const int tid = threadIdx.x;
    const int lane = tid & 31, warp = tid >> 5;
    const int grp = lane >> 2, qid = lane & 3;

    if (tid < 224) {
        const int ks = tid >> 5, ln = tid & 31;
        const int g2 = ln >> 2, q2 = ln & 3;
        float v[4];
        #pragma unroll
        for (int nt = 0; nt < 2; ++nt)
            #pragma unroll
            for (int h = 0; h < 2; ++h) {
                const int k = 8 * ks + q2 + 4 * h;
                v[2 * nt + h] = (k < 50)
                    ? __uint_as_float(to_tf32(wts[(g2 + 8 * nt) * 50 + k])) : 0.f;
            }
        *reinterpret_cast<float4*>(Bf + tid * 4) = *reinterpret_cast<float4*>(v);
    }
    if (tid < 16) bsm[tid] = bias[tid];
    if (tid < 56) {
        const int ic = tid / 25, tap = tid % 25;
        offs[tid] = (tid < 50)
            ? ic * (C1_TR * C1_WP) + (tap / 5) * C1_WP + (tap % 5) : 0;
    }

    const float inv0 = 1.f / __uint_as_float(g_immax[img * 2]);
    const float inv1 = 1.f / __uint_as_float(g_immax[img * 2 + 1]);
    const int iy0 = 10 * rg - 2;
    for (int i = tid; i < C1_TILE; i += 256) {
        const int ic = i / (C1_TR * C1_WP);
        const int r  = (i / C1_WP) % C1_TR;
        const int c  = i % C1_WP;
        const int iy = iy0 + r, ix = c - 2;
        float v = 0.f;
        if (iy >= 0 && iy < 100 && ix >= 0 && ix < 100)
            v = g_imgs[(img * 2 + ic) * (DD * DD) + iy * DD + ix]
                * (ic ? inv1 : inv0);
        tile[i] = __uint_as_float(to_tf32(v));
    }
    __syncthreads();

    int abase[8][2];
    #pragma unroll
    for (int t = 0; t < 8; ++t) {
        const int mt = warp + 8 * t;
        #pragma unroll
        for (int h = 0; h < 2; ++h) {
            int m = mt * 16 + grp + 8 * h;
            if (m > 999) m = 999;
            abase[t][h] = (m / 100) * C1_WP + (m % 100);
        }
    }

    float acc[8][2][4];
    #pragma unroll
    for (int t = 0; t < 8; ++t)
        #pragma unroll
        for (int nt = 0; nt < 2; ++nt)
            acc[t][nt][0] = acc[t][nt][1] = acc[t][nt][2] = acc[t][nt][3] = 0.f;

    #pragma unroll
    for (int ks = 0; ks < 7; ++ks) {
        const int o0 = offs[ks * 8 + qid];
        const int o1 = offs[ks * 8 + qid + 4];
        const float4 bv = *reinterpret_cast<const float4*>(
            Bf + (ks * 32 + lane) * 4);
        uint32_t b[2][2];
        b[0][0] = __float_as_uint(bv.x); b[0][1] = __float_as_uint(bv.y);
        b[1][0] = __float_as_uint(bv.z); b[1][1] = __float_as_uint(bv.w);

        #pragma unroll
        for (int t = 0; t < 8; ++t) {
            if (warp + 8 * t < 63) {
                uint32_t a[4];
                a[0] = __float_as_uint(tile[abase[t][0] + o0]);
                a[1] = __float_as_uint(tile[abase[t][1] + o0]);
                a[2] = __float_as_uint(tile[abase[t][0] + o1]);
                a[3] = __float_as_uint(tile[abase[t][1] + o1]);
                mma_tf32(acc[t][0], a, b[0]);
                mma_tf32(acc[t][1], a, b[1]);
            }
        }
    }
    __syncthreads();

    #pragma unroll
    for (int t = 0; t < 8; ++t) {
        const int mt = warp + 8 * t;
        if (mt < 63) {
            const int m0 = mt * 16 + grp;
            #pragma unroll
            for (int nt = 0; nt < 2; ++nt) {
                const int n0 = nt * 8 + 2 * qid;
                Cs[m0 * 17 + n0]           = acc[t][nt][0];
                Cs[m0 * 17 + n0 + 1]       = acc[t][nt][1];
                Cs[(m0 + 8) * 17 + n0]     = acc[t][nt][2];
                Cs[(m0 + 8) * 17 + n0 + 1] = acc[t][nt][3];
            }
        }
    }
    __syncthreads();

    for (int idx = tid; idx < 4000; idx += 256) {
        const int oc = idx & 15;
        const int pc = (idx >> 4) % 50;
        const int prl = idx / 800;
        const int prow = 5 * rg + prl;
        const int m00 = 2 * prl * 100 + 2 * pc;
        float v = fmaxf(fmaxf(Cs[m00 * 17 + oc],         Cs[(m00 + 1) * 17 + oc]),
                        fmaxf(Cs[(m00 + 100) * 17 + oc], Cs[(m00 + 101) * 17 + oc]));
        v = fmaxf(v + bsm[oc], 0.f);
        g_y1[((img * 16 + oc) * 50 + prow) * 50 + pc] = v;
    }
}

// ============= K4: conv2 tf32 TC (R9 proven) + FUSED FC HEAD ================
#define C2_TR   10
#define C2_TILE (16 * C2_TR * 57)                           // 9120
#define C2_SMEM_FLOATS (C2_TILE + 50 * 32 * 8 + 400 + 32)   // 22352
__global__ __launch_bounds__(256, 2) void conv2_tc_kernel(
    const float* __restrict__ wts, const float* __restrict__ bias,
    const float* __restrict__ out_w, const float* __restrict__ out_b,
    float* __restrict__ out)
{
    extern __shared__ float s[];
    float* tile = s;                          // [16][10][57]
    float* Bf   = tile + C2_TILE;             // [50][32][8]
    int*   offs = (int*)(Bf + 50 * 32 * 8);   // [400]
    float* bsm  = (float*)(offs + 400);       // [32]
    float* Cs   = s;                          // [304][33] alias (post-mainloop)

    const int img = blockIdx.x;
    const int rg  = blockIdx.y;               // 3-pooled-row group (0..8)
    const int tid = threadIdx.x;
    const int lane = tid & 31, warp = tid >> 5;
    const int grp = lane >> 2, qid = lane & 3;

    for (int idx = tid; idx < 50 * 32; idx += 256) {
        const int ks = idx >> 5, ln = idx & 31;
        const int g2 = ln >> 2, q2 = ln & 3;
        float v[8];
        #pragma unroll
        for (int nt = 0; nt < 4; ++nt) {
            const float* wp = wts + (g2 + 8 * nt) * 400 + 8 * ks + q2;
            v[2 * nt]     = __uint_as_float(to_tf32(wp[0]));
            v[2 * nt + 1] = __uint_as_float(to_tf32(wp[4]));
        }
        float* dst = Bf + idx * 8;
        *reinterpret_cast<float4*>(dst)     = *reinterpret_cast<float4*>(v);
        *reinterpret_cast<float4*>(dst + 4) = *reinterpret_cast<float4*>(v + 4);
    }
    if (tid < 32) bsm[tid] = bias[tid];
    for (int k = tid; k < 400; k += 256) {
        int ic = k / 25, kk = k % 25;
        offs[k] = ic * (C2_TR * 57) + (kk / 5) * 57 + (kk % 5);
    }
    const int iy0 = 6 * rg - 2;
    for (int i = tid; i < C2_TILE; i += 256) {
        int ic = i / (C2_TR * 57), r = (i / 57) % C2_TR, c = i % 57;
        int iy = iy0 + r, ix = c - 2;
        float v = 0.f;
        if (iy >= 0 && iy < 50 && ix >= 0 && ix < 50)
            v = g_y1[((img * 16 + ic) * 50 + iy) * 50 + ix];
        tile[i] = __uint_as_float(to_tf32(v));
    }
    __syncthreads();

    int abase[3][2];
    int nvalid = 0;
    #pragma unroll
    for (int t = 0; t < 3; ++t) {
        const int mt = warp + 8 * t;
        if (mt < 19) nvalid = t + 1;
        #pragma unroll
        for (int h = 0; h < 2; ++h) {
            int m = mt * 16 + grp + h * 8;
            if (m > 299) m = 299;
            abase[t][h] = (m / 50) * 57 + (m % 50);
        }
    }

    float acc[3][4][4];
    #pragma unroll
    for (int t = 0; t < 3; ++t)
        #pragma unroll
        for (int nt = 0; nt < 4; ++nt)
            acc[t][nt][0] = acc[t][nt][1] = acc[t][nt][2] = acc[t][nt][3] = 0.f;

    #pragma unroll 2
    for (int ks = 0; ks < 50; ++ks) {
        const int o0 = offs[ks * 8 + qid];
        const int o1 = offs[ks * 8 + qid + 4];

        const float4* bp = reinterpret_cast<const float4*>(
            Bf + (ks * 32 + lane) * 8);
        float4 bv0 = bp[0], bv1 = bp[1];
        uint32_t b[4][2];
        b[0][0] = __float_as_uint(bv0.x); b[0][1] = __float_as_uint(bv0.y);
        b[1][0] = __float_as_uint(bv0.z); b[1][1] = __float_as_uint(bv0.w);
        b[2][0] = __float_as_uint(bv1.x); b[2][1] = __float_as_uint(bv1.y);
        b[3][0] = __float_as_uint(bv1.z); b[3][1] = __float_as_uint(bv1.w);

        #pragma unroll
        for (int t = 0; t < 3; ++t) {
            if (t < nvalid) {
                uint32_t a[4];
                a[0] = __float_as_uint(tile[abase[t][0] + o0]);
                a[1] = __float_as_uint(tile[abase[t][1] + o0]);
                a[2] = __float_as_uint(tile[abase[t][0] + o1]);
                a[3] = __float_as_uint(tile[abase[t][1] + o1]);
                #pragma unroll
                for (int nt = 0; nt < 4; ++nt)
                    mma_tf32(acc[t][nt], a, b[nt]);
            }
        }
    }

    __syncthreads();   // tile/Bf reads done; Cs may overwrite

    #pragma unroll
    for (int t = 0; t < 3; ++t) {
        const int mt = warp + 8 * t;
        if (mt < 19) {
            const int m0 = mt * 16 + grp;
            #pragma unroll
            for (int nt = 0; nt < 4; ++nt) {
                const int n0 = nt * 8 + 2 * qid;
                Cs[m0 * 33 + n0]           = acc[t][nt][0];
                Cs[m0 * 33 + n0 + 1]       = acc[t][nt][1];
                Cs[(m0 + 8) * 33 + n0]     = acc[t][nt][2];
                Cs[(m0 + 8) * 33 + n0 + 1] = acc[t][nt][3];
            }
        }
    }
    __syncthreads();

    // Epilogue: bias + 2x2 maxpool + relu -> fused FC partials.
    float p[NCLS];
    #pragma unroll
    for (int c = 0; c < NCLS; ++c) p[c] = 0.f;

    for (int idx = tid; idx < 2400; idx += 256) {
        const int pc  = idx % 25;
        const int prl = (idx / 25) % 3;
        const int oc  = idx / 75;
        const int prow = 3 * rg + prl;
        if (prow < 25) {
            const int m00 = 2 * prl * 50 + 2 * pc;
            float v = fmaxf(fmaxf(Cs[m00 * 33 + oc],        Cs[(m00 + 1) * 33 + oc]),
                            fmaxf(Cs[(m00 + 50) * 33 + oc], Cs[(m00 + 51) * 33 + oc]));
            v = fmaxf(v + bsm[oc], 0.f);
            const int flat = oc * 625 + prow * 25 + pc;
            #pragma unroll
            for (int c = 0; c < NCLS; ++c)
                p[c] += v * out_w[c * 20000 + flat];
        }
    }
    __syncthreads();   // Cs reads done; reuse s for reduction

    #pragma unroll
    for (int c = 0; c < NCLS; ++c) {
        #pragma unroll
        for (int off = 16; off; off >>= 1)
            p[c] += __shfl_down_sync(0xffffffffu, p[c], off);
    }
    if (lane == 0) {
        #pragma unroll
        for (int c = 0; c < NCLS; ++c) s[warp * NCLS + c] = p[c];
    }
    __syncthreads();
    if (tid < NCLS) {
        float t = 0.f;
        #pragma unroll
        for (int w = 0; w < 8; ++w) t += s[w * NCLS + tid];
        if (rg == 0) t += out_b[tid];     // bias added exactly once per (img,c)
        atomicAdd(&out[img * NCLS + tid], t);
    }
}

// ============================== launch ======================================
extern "C" void kernel_launch(void* const* d_in, const int* in_sizes, int n_in,
                              void* d_out, int out_size)
{
    const float* x        = (const float*)d_in[0];
    const int*   pidx0    = (const int*)  d_in[1];
    const int*   pidx1    = (const int*)  d_in[2];
    const float* w1       = (const float*)d_in[3];
    const float* b1       = (const float*)d_in[4];
    const float* w2       = (const float*)d_in[5];
    const float* b2       = (const float*)d_in[6];
    const float* conv1_w  = (const float*)d_in[7];
    const float* conv1_b  = (const float*)d_in[8];
    const float* conv2_w  = (const float*)d_in[9];
    const float* conv2_b  = (const float*)d_in[10];
    const float* out_w    = (const float*)d_in[11];
    const float* out_b    = (const float*)d_in[12];
    float* out = (float*)d_out;

    const int pers_smem  = PERS_SMEM_FLOATS * 4;   // 66816
    const int conv1_smem = C1_SMEM_FLOATS * 4;     // 68608
    const int conv2_smem = C2_SMEM_FLOATS * 4;     // 89408

    cudaFuncSetAttribute(pers_image_kernel,
        cudaFuncAttributeMaxDynamicSharedMemorySize, pers_smem);
    cudaFuncSetAttribute(conv1_tc_kernel,
        cudaFuncAttributeMaxDynamicSharedMemorySize, conv1_smem);
    cudaFuncSetAttribute(conv2_tc_kernel,
        cudaFuncAttributeMaxDynamicSharedMemorySize, conv2_smem);

    // K1: node filtration -> g_filt and d_out[320:]; zeroes d_out[0:320]+g_immax
    filt_kernel<<<250, 256>>>(x, w1, b1, w2, b2, out);

    // K2: persistence images (unnormalized) + per-imgch max, 256 blocks
    pers_image_kernel<<<256, 256, pers_smem>>>(pidx0, pidx1);

    // K3: conv1 via tf32 TC (+fused normalization) -> g_y1
    conv1_tc_kernel<<<dim3(32, 10), 256, conv1_smem>>>(conv1_w, conv1_b);

    // K4: conv2 via tf32 TC + fused FC head -> d_out[0:320]
    conv2_tc_kernel<<<dim3(32, 9), 256, conv2_smem>>>(
        conv2_w, conv2_b, out_w, out_b, out);
}

// round 16
// speedup vs baseline: 1.2837x; 1.1855x over previous
#include <cuda_runtime.h>
#include <cstdint>

#define NN     16000
#define IN_DIM 128
#define HID    64
#define BB     32
#define PP     128
#define DD     100
#define NCLS   10
#define INV_PI 0.31830988618379067f

// ---------------- scratch (device globals; no allocation allowed) -----------
__device__ float    g_filt[NN];
__device__ float    g_imgs[BB * 2 * DD * DD];    // UNNORMALIZED pers images
__device__ unsigned g_immax[BB * 2];             // per image-channel max (fp bits)
__device__ float    g_y1[BB * 16 * 50 * 50];

// ================== tf32 helpers (shared by all TC kernels) =================
__device__ __forceinline__ uint32_t to_tf32(float x) {
    uint32_t r;
    asm("cvt.rna.tf32.f32 %0, %1;" : "=r"(r) : "f"(x));
    return r;
}
__device__ __forceinline__ void mma_tf32(
    float* d, const uint32_t* a, const uint32_t* b)
{
    asm volatile(
        "mma.sync.aligned.m16n8k8.row.col.f32.tf32.tf32.f32 "
        "{%0,%1,%2,%3}, {%4,%5,%6,%7}, {%8,%9}, {%0,%1,%2,%3};\n"
        : "+f"(d[0]), "+f"(d[1]), "+f"(d[2]), "+f"(d[3])
        : "r"(a[0]), "r"(a[1]), "r"(a[2]), "r"(a[3]),
          "r"(b[0]), "r"(b[1]));
}

// ======================= K1: node filtration MLP (tf32 TC) ==================
// M=16000 (125 CTAs x 128 rows), K=128 (16 ks), N=64 (8 n-tiles).
// Warp w owns m-tile w. Epilogue: +b1, relu, *w2, quad row-sum, sigmoid.
// Bf layout: 4 conflict-free [32][4] blocks per ks (16B lane stride).
#define F_XSTR 132
#define FILT_SMEM_FLOATS (128 * F_XSTR + 16 * 4 * 128 + 64 + 64)   // 25216
__global__ __launch_bounds__(256, 2) void filt_tc_kernel(
    const float* __restrict__ x, const float* __restrict__ w1,
    const float* __restrict__ b1, const float* __restrict__ w2,
    const float* __restrict__ b2, float* __restrict__ out)
{
    extern __shared__ float s[];
    float* xs  = s;                        // [128][132]
    float* Bf  = xs + 128 * F_XSTR;        // [16*4][128]
    float* b1s = Bf + 16 * 4 * 128;        // [64]
    float* w2s = b1s + 64;                 // [64]

    const int cta = blockIdx.x;
    const int tid = threadIdx.x;
    const int lane = tid & 31, warp = tid >> 5;
    const int grp = lane >> 2, qid = lane & 3;

    if (cta == 0) {
        if (tid < BB * 2) g_immax[tid] = 0u;
        for (int i = tid; i < BB * NCLS; i += 256) out[i] = 0.f;
    }

    // Bf[(ks*4+q)*128 + ln*4 + e] covers nt = 2q + (e>>1), k-half = e&1
    for (int idx = tid; idx < 16 * 32; idx += 256) {
        const int ks = idx >> 5, ln = idx & 31;
        const int g2 = ln >> 2, q2 = ln & 3;
        #pragma unroll
        for (int q = 0; q < 4; ++q) {
            float v[4];
            #pragma unroll
            for (int e = 0; e < 4; ++e) {
                const int nt = 2 * q + (e >> 1);
                const int h  = e & 1;
                const int k  = 8 * ks + q2 + 4 * h;
                v[e] = __uint_as_float(to_tf32(w1[k * HID + g2 + 8 * nt]));
            }
            *reinterpret_cast<float4*>(Bf + (ks * 4 + q) * 128 + ln * 4) =
                *reinterpret_cast<float4*>(v);
        }
    }
    if (tid < 64) { b1s[tid] = b1[tid]; w2s[tid] = w2[tid]; }
    const float b2v = b2[0];

    // xs: 128 rows x 128 cols, tf32-rounded, float4 loads/stores
    const float4* xg = reinterpret_cast<const float4*>(x + cta * 128 * IN_DIM);
    for (int i4 = tid; i4 < 128 * 32; i4 += 256) {
        const int row = i4 >> 5, c4 = i4 & 31;
        float4 v = xg[i4];
        v.x = __uint_as_float(to_tf32(v.x));
        v.y = __uint_as_float(to_tf32(v.y));
        v.z = __uint_as_float(to_tf32(v.z));
        v.w = __uint_as_float(to_tf32(v.w));
        *reinterpret_cast<float4*>(xs + row * F_XSTR + c4 * 4) = v;
    }
    __syncthreads();

    const int r0 = warp * 16 + grp;
    float acc[8][4];
    #pragma unroll
    for (int nt = 0; nt < 8; ++nt)
        acc[nt][0] = acc[nt][1] = acc[nt][2] = acc[nt][3] = 0.f;

    #pragma unroll
    for (int ks = 0; ks < 16; ++ks) {
        const int k = 8 * ks + qid;
        uint32_t a[4];
        a[0] = __float_as_uint(xs[r0 * F_XSTR + k]);
        a[1] = __float_as_uint(xs[(r0 + 8) * F_XSTR + k]);
        a[2] = __float_as_uint(xs[r0 * F_XSTR + k + 4]);
        a[3] = __float_as_uint(xs[(r0 + 8) * F_XSTR + k + 4]);
        #pragma unroll
        for (int q = 0; q < 4; ++q) {
            const float4 bv = *reinterpret_cast<const float4*>(
                Bf + (ks * 4 + q) * 128 + lane * 4);
            uint32_t b0[2] = { __float_as_uint(bv.x), __float_as_uint(bv.y) };
            uint32_t b1r[2] = { __float_as_uint(bv.z), __float_as_uint(bv.w) };
            mma_tf32(acc[2 * q],     a, b0);
            mma_tf32(acc[2 * q + 1], a, b1r);
        }
    }

    // epilogue: rows r0 and r0+8
    float s0 = 0.f, s1 = 0.f;
    #pragma unroll
    for (int nt = 0; nt < 8; ++nt) {
        const int n0 = 8 * nt + 2 * qid;
        s0 += fmaxf(acc[nt][0] + b1s[n0],     0.f) * w2s[n0]
            + fmaxf(acc[nt][1] + b1s[n0 + 1], 0.f) * w2s[n0 + 1];
        s1 += fmaxf(acc[nt][2] + b1s[n0],     0.f) * w2s[n0]
            + fmaxf(acc[nt][3] + b1s[n0 + 1], 0.f) * w2s[n0 + 1];
    }
    s0 += __shfl_xor_sync(0xffffffffu, s0, 1);
    s0 += __shfl_xor_sync(0xffffffffu, s0, 2);
    s1 += __shfl_xor_sync(0xffffffffu, s1, 1);
    s1 += __shfl_xor_sync(0xffffffffu, s1, 2);
    if (qid == 0) {
        const int m = cta * 128 + r0;
        float f0 = 1.f / (1.f + __expf(-(s0 + b2v)));
        float f1 = 1.f / (1.f + __expf(-(s1 + b2v)));
        g_filt[m]     = f0;  out[BB * NCLS + m]     = f0;
        g_filt[m + 8] = f1;  out[BB * NCLS + m + 8] = f1;
    }
}

// ================ K2: persistence image (quarter blocks, atomic max) ========
#define P_UW 28
#define PERS_SMEM_FLOATS (PP * P_UW + PP * DD + PP + PP + 32)
__global__ __launch_bounds__(256) void pers_image_kernel(
    const int* __restrict__ pidx0, const int* __restrict__ pidx1)
{
    extern __shared__ float sm[];
    float* Us = sm;                 // [128][28]
    float* Vs = Us + PP * P_UW;     // [128][100]
    float* bs = Vs + PP * DD;
    float* ps = bs + PP;
    float* red = ps + PP;

    const int m     = blockIdx.x;
    const int imgch = m >> 2;
    const int q     = m & 3;
    const int b  = imgch >> 1;
    const int ch = imgch & 1;
    const int* pidx = ch ? pidx1 : pidx0;
    const int tid = threadIdx.x;

    const int itile0  = (q == 0) ? 0 : (7 + 6 * (q - 1));   // 0,7,13,19
    const int ntilesI = (q == 0) ? 7 : 6;
    const int ibase   = itile0 * 4;
    const int iwidth  = ntilesI * 4;

    if (tid < PP) {
        int i0 = pidx[(b * PP + tid) * 2 + 0];
        int i1 = pidx[(b * PP + tid) * 2 + 1];
        float birth = g_filt[i0];
        bs[tid] = birth;
        ps[tid] = g_filt[i1] - birth;
    }
    __syncthreads();

    for (int idx = tid; idx < PP * P_UW; idx += 256) {
        int p = idx / P_UW, t = idx % P_UW;
        float c  = (float)(ibase + t) * 0.01f;
        float db = bs[p] - c;
        Us[idx] = (t < iwidth) ? __expf(-db * db) : 0.f;
    }
    for (int idx = tid; idx < PP * DD; idx += 256) {
        int p = idx / DD, t = idx % DD;
        float c  = (float)t * 0.01f;
        float dp = ps[p] - c;
        Vs[idx] = INV_PI * __expf(-dp * dp);
    }
    __syncthreads();

    const int nt = ntilesI * 25;
    float acc[16];
    float mx = 0.f;
    int i0 = 0, j0 = 0;
    if (tid < nt) {
        i0 = (tid / 25) * 4;
        j0 = (tid % 25) * 4;
        #pragma unroll
        for (int k = 0; k < 16; ++k) acc[k] = 0.f;
        #pragma unroll 4
        for (int p = 0; p < PP; ++p) {
            float4 u = *reinterpret_cast<const float4*>(Us + p * P_UW + i0);
            float4 v = *reinterpret_cast<const float4*>(Vs + p * DD + j0);
            acc[0]  += u.x * v.x; acc[1]  += u.x * v.y; acc[2]  += u.x * v.z; acc[3]  += u.x * v.w;
            acc[4]  += u.y * v.x; acc[5]  += u.y * v.y; acc[6]  += u.y * v.z; acc[7]  += u.y * v.w;
            acc[8]  += u.z * v.x; acc[9]  += u.z * v.y; acc[10] += u.z * v.z; acc[11] += u.z * v.w;
            acc[12] += u.w * v.x; acc[13] += u.w * v.y; acc[14] += u.w * v.z; acc[15] += u.w * v.w;
        }
        #pragma unroll
        for (int k = 0; k < 16; ++k) mx = fmaxf(mx, acc[k]);
    }
    #pragma unroll
    for (int off = 16; off; off >>= 1)
        mx = fmaxf(mx, __shfl_down_sync(0xffffffffu, mx, off));
    if ((tid & 31) == 0) red[tid >> 5] = mx;
    __syncthreads();
    if (tid == 0) {
        float t = red[0];
        #pragma unroll
        for (int w = 1; w < 8; ++w) t = fmaxf(t, red[w]);
        atomicMax(&g_immax[imgch], __float_as_uint(t));
    }

    if (tid < nt) {
        float* outp = g_imgs + imgch * (DD * DD);
        #pragma unroll
        for (int a = 0; a < 4; ++a)
            #pragma unroll
            for (int c = 0; c < 4; ++c)
                outp[(ibase + i0 + a) * DD + (j0 + c)] = acc[a * 4 + c];
    }
}

// ============= K3: conv1 tf32 TC implicit GEMM (+fused normalization) =======
#define C1_TR   14
#define C1_WP   104
#define C1_TILE (2 * C1_TR * C1_WP)            // 2912
#define C1_CS   (1008 * 17)                    // 17136
#define C1_SMEM_FLOATS (C1_CS + 16)
__global__ __launch_bounds__(256, 2) void conv1_tc_kernel(
    const float* __restrict__ wts, const float* __restrict__ bias)
{
    extern __shared__ float s[];
    float* tile = s;                           // [2][14][104] (mainloop)
    float* Bf   = tile + C1_TILE;              // [7][32][4]
    int*   offs = (int*)(Bf + 7 * 32 * 4);     // [56]
    float* Cs   = s;                           // [1008][17] (post-mainloop)
    float* bsm  = s + C1_CS;                   // [16]

    const int img = blockIdx.x;
    const int rg  = blockIdx.y;
    const int tid = threadIdx.x;
    const int lane = tid & 31, warp = tid >> 5;
    const int grp = lane >> 2, qid = lane & 3;

    if (tid < 224) {
        const int ks = tid >> 5, ln = tid & 31;
        const int g2 = ln >> 2, q2 = ln & 3;
        float v[4];
        #pragma unroll
        for (int nt = 0; nt < 2; ++nt)
            #pragma unroll
            for (int h = 0; h < 2; ++h) {
                const int k = 8 * ks + q2 + 4 * h;
                v[2 * nt + h] = (k < 50)
                    ? __uint_as_float(to_tf32(wts[(g2 + 8 * nt) * 50 + k])) : 0.f;
            }
        *reinterpret_cast<float4*>(Bf + tid * 4) = *reinterpret_cast<float4*>(v);
    }
    if (tid < 16) bsm[tid] = bias[tid];
    if (tid < 56) {
        const int ic = tid / 25, tap = tid % 25;
        offs[tid] = (tid < 50)
            ? ic * (C1_TR * C1_WP) + (tap / 5) * C1_WP + (tap % 5) : 0;
    }

    const float inv0 = 1.f / __uint_as_float(g_immax[img * 2]);
    const float inv1 = 1.f / __uint_as_float(g_immax[img * 2 + 1]);
    const int iy0 = 10 * rg - 2;
    for (int i = tid; i < C1_TILE; i += 256) {
        const int ic = i / (C1_TR * C1_WP);
        const int r  = (i / C1_WP) % C1_TR;
        const int c  = i % C1_WP;
        const int iy = iy0 + r, ix = c - 2;
        float v = 0.f;
        if (iy >= 0 && iy < 100 && ix >= 0 && ix < 100)
            v = g_imgs[(img * 2 + ic) * (DD * DD) + iy * DD + ix]
                * (ic ? inv1 : inv0);
        tile[i] = __uint_as_float(to_tf32(v));
    }
    __syncthreads();

    int abase[8][2];
    #pragma unroll
    for (int t = 0; t < 8; ++t) {
        const int mt = warp + 8 * t;
        #pragma unroll
        for (int h = 0; h < 2; ++h) {
            int m = mt * 16 + grp + 8 * h;
            if (m > 999) m = 999;
            abase[t][h] = (m / 100) * C1_WP + (m % 100);
        }
    }

    float acc[8][2][4];
    #pragma unroll
    for (int t = 0; t < 8; ++t)
        #pragma unroll
        for (int nt = 0; nt < 2; ++nt)
            acc[t][nt][0] = acc[t][nt][1] = acc[t][nt][2] = acc[t][nt][3] = 0.f;

    #pragma unroll
    for (int ks = 0; ks < 7; ++ks) {
        const int o0 = offs[ks * 8 + qid];
        const int o1 = offs[ks * 8 + qid + 4];
        const float4 bv = *reinterpret_cast<const float4*>(
            Bf + (ks * 32 + lane) * 4);
        uint32_t b[2][2];
        b[0][0] = __float_as_uint(bv.x); b[0][1] = __float_as_uint(bv.y);
        b[1][0] = __float_as_uint(bv.z); b[1][1] = __float_as_uint(bv.w);

        #pragma unroll
        for (int t = 0; t < 8; ++t) {
            if (warp + 8 * t < 63) {
                uint32_t a[4];
                a[0] = __float_as_uint(tile[abase[t][0] + o0]);
                a[1] = __float_as_uint(tile[abase[t][1] + o0]);
                a[2] = __float_as_uint(tile[abase[t][0] + o1]);
                a[3] = __float_as_uint(tile[abase[t][1] + o1]);
                mma_tf32(acc[t][0], a, b[0]);
                mma_tf32(acc[t][1], a, b[1]);
            }
        }
    }
    __syncthreads();

    #pragma unroll
    for (int t = 0; t < 8; ++t) {
        const int mt = warp + 8 * t;
        if (mt < 63) {
            const int m0 = mt * 16 + grp;
            #pragma unroll
            for (int nt = 0; nt < 2; ++nt) {
                const int n0 = nt * 8 + 2 * qid;
                Cs[m0 * 17 + n0]           = acc[t][nt][0];
                Cs[m0 * 17 + n0 + 1]       = acc[t][nt][1];
                Cs[(m0 + 8) * 17 + n0]     = acc[t][nt][2];
                Cs[(m0 + 8) * 17 + n0 + 1] = acc[t][nt][3];
            }
        }
    }
    __syncthreads();

    for (int idx = tid; idx < 4000; idx += 256) {
        const int oc = idx & 15;
        const int pc = (idx >> 4) % 50;
        const int prl = idx / 800;
        const int prow = 5 * rg + prl;
        const int m00 = 2 * prl * 100 + 2 * pc;
        float v = fmaxf(fmaxf(Cs[m00 * 17 + oc],         Cs[(m00 + 1) * 17 + oc]),
                        fmaxf(Cs[(m00 + 100) * 17 + oc], Cs[(m00 + 101) * 17 + oc]));
        v = fmaxf(v + bsm[oc], 0.f);
        g_y1[((img * 16 + oc) * 50 + prow) * 50 + pc] = v;
    }
}

// ============= K4: conv2 tf32 TC + fused FC head ============================
// Bf laid as two [32][4] blocks per ks -> 16B lane stride, conflict-free.
#define C2_TR   10
#define C2_TILE (16 * C2_TR * 57)                           // 9120
#define C2_SMEM_FLOATS (C2_TILE + 50 * 32 * 8 + 400 + 32)   // 22352
__global__ __launch_bounds__(256, 2) void conv2_tc_kernel(
    const float* __restrict__ wts, const float* __restrict__ bias,
    const float* __restrict__ out_w, const float* __restrict__ out_b,
    float* __restrict__ out)
{
    extern __shared__ float s[];
    float* tile = s;                          // [16][10][57]
    float* Bf   = tile + C2_TILE;             // [100][128]
    int*   offs = (int*)(Bf + 50 * 32 * 8);   // [400]
    float* bsm  = (float*)(offs + 400);       // [32]
    float* Cs   = s;                          // [304][33] alias (post-mainloop)

    const int img = blockIdx.x;
    const int rg  = blockIdx.y;               // 3-pooled-row group (0..8)
    const int tid = threadIdx.x;
    const int lane = tid & 31, warp = tid >> 5;
    const int grp = lane >> 2, qid = lane & 3;

    for (int idx = tid; idx < 50 * 32; idx += 256) {
        const int ks = idx >> 5, ln = idx & 31;
        const int g2 = ln >> 2, q2 = ln & 3;
        float v[8];
        #pragma unroll
        for (int nt = 0; nt < 4; ++nt) {
            const float* wp = wts + (g2 + 8 * nt) * 400 + 8 * ks + q2;
            v[2 * nt]     = __uint_as_float(to_tf32(wp[0]));
            v[2 * nt + 1] = __uint_as_float(to_tf32(wp[4]));
        }
        *reinterpret_cast<float4*>(Bf + (ks * 2) * 128 + ln * 4) =
            *reinterpret_cast<float4*>(v);
        *reinterpret_cast<float4*>(Bf + (ks * 2 + 1) * 128 + ln * 4) =
            *reinterpret_cast<float4*>(v + 4);
    }
    if (tid < 32) bsm[tid] = bias[tid];
    for (int k = tid; k < 400; k += 256) {
        int ic = k / 25, kk = k % 25;
        offs[k] = ic * (C2_TR * 57) + (kk / 5) * 57 + (kk % 5);
    }
    const int iy0 = 6 * rg - 2;
    for (int i = tid; i < C2_TILE; i += 256) {
        int ic = i / (C2_TR * 57), r = (i / 57) % C2_TR, c = i % 57;
        int iy = iy0 + r, ix = c - 2;
        float v = 0.f;
        if (iy >= 0 && iy < 50 && ix >= 0 && ix < 50)
            v = g_y1[((img * 16 + ic) * 50 + iy) * 50 + ix];
        tile[i] = __uint_as_float(to_tf32(v));
    }
    __syncthreads();

    int abase[3][2];
    int nvalid = 0;
    #pragma unroll
    for (int t = 0; t < 3; ++t) {
        const int mt = warp + 8 * t;
        if (mt < 19) nvalid = t + 1;
        #pragma unroll
        for (int h = 0; h < 2; ++h) {
            int m = mt * 16 + grp + h * 8;
            if (m > 299) m = 299;
            abase[t][h] = (m / 50) * 57 + (m % 50);
        }
    }

    float acc[3][4][4];
    #pragma unroll
    for (int t = 0; t < 3; ++t)
        #pragma unroll
        for (int nt = 0; nt < 4; ++nt)
            acc[t][nt][0] = acc[t][nt][1] = acc[t][nt][2] = acc[t][nt][3] = 0.f;

    #pragma unroll 2
    for (int ks = 0; ks < 50; ++ks) {
        const int o0 = offs[ks * 8 + qid];
        const int o1 = offs[ks * 8 + qid + 4];

        const float4 bv0 = *reinterpret_cast<const float4*>(
            Bf + (ks * 2) * 128 + lane * 4);
        const float4 bv1 = *reinterpret_cast<const float4*>(
            Bf + (ks * 2 + 1) * 128 + lane * 4);
        uint32_t b[4][2];
        b[0][0] = __float_as_uint(bv0.x); b[0][1] = __float_as_uint(bv0.y);
        b[1][0] = __float_as_uint(bv0.z); b[1][1] = __float_as_uint(bv0.w);
        b[2][0] = __float_as_uint(bv1.x); b[2][1] = __float_as_uint(bv1.y);
        b[3][0] = __float_as_uint(bv1.z); b[3][1] = __float_as_uint(bv1.w);

        #pragma unroll
        for (int t = 0; t < 3; ++t) {
            if (t < nvalid) {
                uint32_t a[4];
                a[0] = __float_as_uint(tile[abase[t][0] + o0]);
                a[1] = __float_as_uint(tile[abase[t][1] + o0]);
                a[2] = __float_as_uint(tile[abase[t][0] + o1]);
                a[3] = __float_as_uint(tile[abase[t][1] + o1]);
                #pragma unroll
                for (int nt = 0; nt < 4; ++nt)
                    mma_tf32(acc[t][nt], a, b[nt]);
            }
        }
    }

    __syncthreads();   // tile/Bf reads done; Cs may overwrite

    #pragma unroll
    for (int t = 0; t < 3; ++t) {
        const int mt = warp + 8 * t;
        if (mt < 19) {
            const int m0 = mt * 16 + grp;
            #pragma unroll
            for (int nt = 0; nt < 4; ++nt) {
                const int n0 = nt * 8 + 2 * qid;
                Cs[m0 * 33 + n0]           = acc[t][nt][0];
                Cs[m0 * 33 + n0 + 1]       = acc[t][nt][1];
                Cs[(m0 + 8) * 33 + n0]     = acc[t][nt][2];
                Cs[(m0 + 8) * 33 + n0 + 1] = acc[t][nt][3];
            }
        }
    }
    __syncthreads();

    // Epilogue: bias + 2x2 maxpool + relu -> fused FC partials.
    float p[NCLS];
    #pragma unroll
    for (int c = 0; c < NCLS; ++c) p[c] = 0.f;

    for (int idx = tid; idx < 2400; idx += 256) {
        const int pc  = idx % 25;
        const int prl = (idx / 25) % 3;
        const int oc  = idx / 75;
        const int prow = 3 * rg + prl;
        if (prow < 25) {
            const int m00 = 2 * prl * 50 + 2 * pc;
            float v = fmaxf(fmaxf(Cs[m00 * 33 + oc],        Cs[(m00 + 1) * 33 + oc]),
                            fmaxf(Cs[(m00 + 50) * 33 + oc], Cs[(m00 + 51) * 33 + oc]));
            v = fmaxf(v + bsm[oc], 0.f);
            const int flat = oc * 625 + prow * 25 + pc;
            #pragma unroll
            for (int c = 0; c < NCLS; ++c)
                p[c] += v * out_w[c * 20000 + flat];
        }
    }
    __syncthreads();   // Cs reads done; reuse s for reduction

    #pragma unroll
    for (int c = 0; c < NCLS; ++c) {
        #pragma unroll
        for (int off = 16; off; off >>= 1)
            p[c] += __shfl_down_sync(0xffffffffu, p[c], off);
    }
    if (lane == 0) {
        #pragma unroll
        for (int c = 0; c < NCLS; ++c) s[warp * NCLS + c] = p[c];
    }
    __syncthreads();
    if (tid < NCLS) {
        float t = 0.f;
        #pragma unroll
        for (int w = 0; w < 8; ++w) t += s[w * NCLS + tid];
        if (rg == 0) t += out_b[tid];     // bias added exactly once per (img,c)
        atomicAdd(&out[img * NCLS + tid], t);
    }
}

// ============================== launch ======================================
extern "C" void kernel_launch(void* const* d_in, const int* in_sizes, int n_in,
                              void* d_out, int out_size)
{
    const float* x        = (const float*)d_in[0];
    const int*   pidx0    = (const int*)  d_in[1];
    const int*   pidx1    = (const int*)  d_in[2];
    const float* w1       = (const float*)d_in[3];
    const float* b1       = (const float*)d_in[4];
    const float* w2       = (const float*)d_in[5];
    const float* b2       = (const float*)d_in[6];
    const float* conv1_w  = (const float*)d_in[7];
    const float* conv1_b  = (const float*)d_in[8];
    const float* conv2_w  = (const float*)d_in[9];
    const float* conv2_b  = (const float*)d_in[10];
    const float* out_w    = (const float*)d_in[11];
    const float* out_b    = (const float*)d_in[12];
    float* out = (float*)d_out;

    const int filt_smem  = FILT_SMEM_FLOATS * 4;   // 100864
    const int pers_smem  = PERS_SMEM_FLOATS * 4;   // 66816
    const int conv1_smem = C1_SMEM_FLOATS * 4;     // 68608
    const int conv2_smem = C2_SMEM_FLOATS * 4;     // 89408

    cudaFuncSetAttribute(filt_tc_kernel,
        cudaFuncAttributeMaxDynamicSharedMemorySize, filt_smem);
    cudaFuncSetAttribute(pers_image_kernel,
        cudaFuncAttributeMaxDynamicSharedMemorySize, pers_smem);
    cudaFuncSetAttribute(conv1_tc_kernel,
        cudaFuncAttributeMaxDynamicSharedMemorySize, conv1_smem);
    cudaFuncSetAttribute(conv2_tc_kernel,
        cudaFuncAttributeMaxDynamicSharedMemorySize, conv2_smem);

    // K1: node filtration (tf32 TC) -> g_filt and d_out[320:]; zeroes accums
    filt_tc_kernel<<<125, 256, filt_smem>>>(x, w1, b1, w2, b2, out);

    // K2: persistence images (unnormalized) + per-imgch max, 256 blocks
    pers_image_kernel<<<256, 256, pers_smem>>>(pidx0, pidx1);

    // K3: conv1 via tf32 TC (+fused normalization) -> g_y1
    conv1_tc_kernel<<<dim3(32, 10), 256, conv1_smem>>>(conv1_w, conv1_b);

    // K4: conv2 via tf32 TC + fused FC head -> d_out[0:320]
    conv2_tc_kernel<<<dim3(32, 9), 256, conv2_smem>>>(
        conv2_w, conv2_b, out_w, out_b, out);
}